// round 16
// baseline (speedup 1.0000x reference)
#include <cuda_runtime.h>
#include <math.h>
#include <stdint.h>

// Problem dims
#define Bsz  128
#define Nn   1024
#define Dd   256
#define Gg   64
#define RELD 16
#define KDc  64
#define Qq   192

#define NBG  (Bsz * Gg)   // 8192

// ---------------- scratch (static device globals; zero-init, no allocs) -----
__device__ float g_pe[Nn * KDc];
__device__ float g_fsym[64 * 144];
__device__ float g_wt2[2048 * 256];               // (c=r*64+p, d) K-major, rna
__device__ float g_wkT[64 * 256];                 // (kd, d) K-major, rna
__device__ float g_qer[Qq * KDc];                 // rna copy of query_emb
__device__ float g_xT[(long)Bsz * Dd * Nn];       // x transposed (b,d,n), rna
__device__ float g_k[(long)Bsz * Nn * KDc];       // keys (rna'd in epilogue)
__device__ float g_gobj[(long)Bsz * Qq * Dd];     // (b*192+q, d), rna
__device__ float g_R[(long)RELD * NBG * 9];       // R[r][bg][n*3+m]

// ---------------- helpers ----------------------------------------------------
__device__ __forceinline__ uint32_t smem_u32(const void* p) {
    uint32_t a;
    asm("{ .reg .u64 t; cvta.to.shared.u64 t, %1; cvt.u32.u64 %0, t; }"
        : "=r"(a) : "l"(p));
    return a;
}
__device__ __forceinline__ float rna_tf32(float x) {
    uint32_t u;
    asm("cvt.rna.tf32.f32 %0, %1;" : "=r"(u) : "f"(x));
    return __uint_as_float(u);
}
__device__ __forceinline__ uint32_t rna_bits(float x) {
    uint32_t u;
    asm("cvt.rna.tf32.f32 %0, %1;" : "=r"(u) : "f"(x));
    return u;
}
__device__ __forceinline__ void cpa16(uint32_t dst, const void* src) {
    asm volatile("cp.async.ca.shared.global [%0], [%1], 16;"
                 :: "r"(dst), "l"(src) : "memory");
}
__device__ __forceinline__ void mma8(float* c, const uint32_t* a, const uint32_t* b) {
    asm volatile(
        "mma.sync.aligned.m16n8k8.row.col.f32.tf32.tf32.f32 "
        "{%0,%1,%2,%3}, {%4,%5,%6,%7}, {%8,%9}, {%0,%1,%2,%3};"
        : "+f"(c[0]), "+f"(c[1]), "+f"(c[2]), "+f"(c[3])
        : "r"(a[0]), "r"(a[1]), "r"(a[2]), "r"(a[3]), "r"(b[0]), "r"(b[1]));
}

// ---------------- tf32 mma.sync NT GEMM (k-projection) -----------------------
template<int BM, int BN, int EPI, bool RNAA, bool WRXT>
__global__ __launch_bounds__((BM / 64) * (BN / 32) * 32, 2)
void mma_gemm(const float* __restrict__ A, const float* __restrict__ B,
              float* __restrict__ C, int K, int N,
              long sA, long sB, long sC, float alpha) {
    constexpr int THREADS = (BM / 64) * (BN / 32) * 32;
    constexpr int WN = BN / 32;
    constexpr int STG = (BM + BN) * 32;
    constexpr int CA = BM * 8 / THREADS;
    constexpr int CB = BN * 8 / THREADS;
    extern __shared__ float sm[];
    const uint32_t smb = smem_u32(sm);

    const int t = threadIdx.x;
    const int wid = t >> 5, lane = t & 31;
    const int l4 = lane >> 2, lm4 = lane & 3;
    const int mBase = (wid / WN) * 64;
    const int nBase = (wid % WN) * 32;

    A += (long)blockIdx.z * sA + (long)(blockIdx.y * BM) * K;
    B += (long)blockIdx.z * sB + (long)(blockIdx.x * BN) * K;
    C += (long)blockIdx.z * sC;

    auto load_stage = [&](int kt, int sb) {
        const int k0 = kt * 32;
        uint32_t ab = smb + sb * (STG * 4);
#pragma unroll
        for (int i = 0; i < CA; i++) {
            int id = t + i * THREADS;
            int row = id >> 3, kb = id & 7;
            uint32_t dst = ab + (uint32_t)((row * 32 + ((kb ^ (row & 7)) << 2)) * 4);
            cpa16(dst, A + (long)row * K + k0 + kb * 4);
        }
        uint32_t bb = ab + BM * 32 * 4;
#pragma unroll
        for (int i = 0; i < CB; i++) {
            int id = t + i * THREADS;
            int row = id >> 3, kb = id & 7;
            uint32_t dst = bb + (uint32_t)((row * 32 + ((kb ^ (row & 7)) << 2)) * 4);
            cpa16(dst, B + (long)row * K + k0 + kb * 4);
        }
        asm volatile("cp.async.commit_group;" ::: "memory");
    };

    float acc[4][4][4] = {};
    const int KT = K / 32;
    load_stage(0, 0);

    for (int kt = 0; kt < KT; kt++) {
        if (kt + 1 < KT) {
            load_stage(kt + 1, (kt + 1) & 1);
            asm volatile("cp.async.wait_group 1;" ::: "memory");
        } else {
            asm volatile("cp.async.wait_group 0;" ::: "memory");
        }
        __syncthreads();
        const float* As = sm + (kt & 1) * STG;
        const float* Bs = As + BM * 32;
#pragma unroll
        for (int ks = 0; ks < 4; ks++) {
            const int cx0 = lm4 + ((((2 * ks) ^ l4) & 7) << 2);
            const int cx1 = lm4 + ((((2 * ks + 1) ^ l4) & 7) << 2);
            uint32_t a[4][4];
#pragma unroll
            for (int mt = 0; mt < 4; mt++) {
                int r = mBase + mt * 16 + l4;
                if (RNAA) {
                    a[mt][0] = rna_bits(As[r * 32 + cx0]);
                    a[mt][1] = rna_bits(As[(r + 8) * 32 + cx0]);
                    a[mt][2] = rna_bits(As[r * 32 + cx1]);
                    a[mt][3] = rna_bits(As[(r + 8) * 32 + cx1]);
                } else {
                    a[mt][0] = __float_as_uint(As[r * 32 + cx0]);
                    a[mt][1] = __float_as_uint(As[(r + 8) * 32 + cx0]);
                    a[mt][2] = __float_as_uint(As[r * 32 + cx1]);
                    a[mt][3] = __float_as_uint(As[(r + 8) * 32 + cx1]);
                }
            }
            uint32_t b[4][2];
#pragma unroll
            for (int nt = 0; nt < 4; nt++) {
                int n = nBase + nt * 8 + l4;
                b[nt][0] = __float_as_uint(Bs[n * 32 + cx0]);
                b[nt][1] = __float_as_uint(Bs[n * 32 + cx1]);
            }
#pragma unroll
            for (int mt = 0; mt < 4; mt++)
#pragma unroll
                for (int nt = 0; nt < 4; nt++)
                    mma8(acc[mt][nt], a[mt], b[nt]);
        }
        if (WRXT) {
            const int b = (blockIdx.y * BM) / Nn;
            const int n0 = (blockIdx.y * BM) % Nn;
            const int d0 = kt * 32;
            float* xt = g_xT + (long)b * Dd * Nn + (long)d0 * Nn + n0;
#pragma unroll
            for (int dk = 0; dk < 32; dk++) {
                int kb = dk >> 2, lm = dk & 3;
                float v = rna_tf32(As[t * 32 + ((kb ^ (t & 7)) << 2) + lm]);
                xt[(long)dk * Nn + t] = v;
            }
        }
        __syncthreads();
    }

    const int gn0 = blockIdx.x * BN + nBase;
#pragma unroll
    for (int mt = 0; mt < 4; mt++) {
        int gr0 = blockIdx.y * BM + mBase + mt * 16 + l4;
#pragma unroll
        for (int h = 0; h < 2; h++) {
            int gr = gr0 + 8 * h;
            float* crow = C + (long)gr * N + gn0;
            const float* pe = (EPI == 1) ? &g_pe[(gr & (Nn - 1)) * KDc + gn0] : (const float*)0;
#pragma unroll
            for (int nt = 0; nt < 4; nt++) {
                int gc = nt * 8 + 2 * lm4;
                float2 v;
                v.x = acc[mt][nt][2 * h + 0] * alpha;
                v.y = acc[mt][nt][2 * h + 1] * alpha;
                if (EPI == 1) { v.x += pe[gc]; v.y += pe[gc + 1]; }
                if (EPI == 1 || EPI == 3) { v.x = rna_tf32(v.x); v.y = rna_tf32(v.y); }
                *(float2*)&crow[gc] = v;
            }
        }
    }
}

// ---------------- fused attention: logits + online softmax + gobj ------------
// Block = (qt in 0..2, b). 512 threads, 16 warps: mw = wid>>2 (4 row-warps of
// 16 rows), nw = wid&3 (logits: 16-col slice; gobj: 64-d slice). 16 n-chunks.
// smem floats: qe[4096] | P[4096] | k[2][4096] | x[2][16384] | pmax[256] |
//              psum[256] | Mrun[64] | Lrun[64]
__global__ __launch_bounds__(512, 1)
void attn_kernel(const float* __restrict__ kg, const float* __restrict__ xT,
                 const float* __restrict__ qe, float* __restrict__ gobj) {
    extern __shared__ float sm[];
    float* Pt   = sm + 4096;
    float* pmax = sm + 49152;
    float* psum = sm + 49408;
    float* Mrun = sm + 49664;
    float* Lrun = sm + 49728;
    const uint32_t smb = smem_u32(sm);
    const int t = threadIdx.x, wid = t >> 5, lane = t & 31;
    const int l4 = lane >> 2, lm4 = lane & 3;
    const int mw = wid >> 2, nw = wid & 3;
    const int qt = blockIdx.x, b = blockIdx.y;

    if (t < 64) { Mrun[t] = -1e30f; Lrun[t] = 0.f; }

    const float* kbase = kg + (long)b * Nn * KDc;
    const float* xbase = xT + (long)b * Dd * Nn;
    const float* qbase = qe + qt * 64 * KDc;

    // qe tile: 64 x 64, two 32-col swizzled panels
#pragma unroll
    for (int i = 0; i < 2; i++) {
        int id = t + i * 512; int row = id >> 4, f4 = id & 15, kp = f4 >> 3, kb = f4 & 7;
        uint32_t dst = smb + (uint32_t)((kp * 2048 + row * 32 + ((kb ^ (row & 7)) << 2)) * 4);
        cpa16(dst, qbase + row * 64 + f4 * 4);
    }
    asm volatile("cp.async.commit_group;" ::: "memory");

    auto load_chunk = [&](int ch, int sb) {
#pragma unroll
        for (int i = 0; i < 2; i++) {        // k: 64 x 64
            int id = t + i * 512; int row = id >> 4, f4 = id & 15, kp = f4 >> 3, kb = f4 & 7;
            uint32_t dst = smb + (uint32_t)((8192 + sb * 4096 + kp * 2048 +
                                             row * 32 + ((kb ^ (row & 7)) << 2)) * 4);
            cpa16(dst, kbase + (long)(ch * 64 + row) * 64 + f4 * 4);
        }
#pragma unroll
        for (int i = 0; i < 8; i++) {        // xT: 256 x 64
            int id = t + i * 512; int row = id >> 4, f4 = id & 15, kp = f4 >> 3, kb = f4 & 7;
            uint32_t dst = smb + (uint32_t)((16384 + sb * 16384 + kp * 8192 +
                                             row * 32 + ((kb ^ (row & 7)) << 2)) * 4);
            cpa16(dst, xbase + (long)row * 1024 + ch * 64 + f4 * 4);
        }
        asm volatile("cp.async.commit_group;" ::: "memory");
    };

    float accg[8][4] = {};
    load_chunk(0, 0);
    __syncthreads();

    for (int ch = 0; ch < 16; ch++) {
        const int sb = ch & 1;
        if (ch + 1 < 16) {
            load_chunk(ch + 1, sb ^ 1);
            asm volatile("cp.async.wait_group 1;" ::: "memory");
        } else {
            asm volatile("cp.async.wait_group 0;" ::: "memory");
        }
        __syncthreads();

        // ---- logits mma: 16(rows this warp) x 32cols, K=64 ----
        float accl[2][4] = {};
#pragma unroll
        for (int kp = 0; kp < 2; kp++) {
            const float* Asm = sm + kp * 2048;
            const float* Bsm = sm + 8192 + sb * 4096 + kp * 2048;
#pragma unroll
            for (int ks = 0; ks < 4; ks++) {
                int cx0 = lm4 + ((((2 * ks) ^ l4) & 7) << 2);
                int cx1 = lm4 + ((((2 * ks + 1) ^ l4) & 7) << 2);
                uint32_t a[4];
                int r = mw * 16 + l4;
                a[0] = __float_as_uint(Asm[r * 32 + cx0]);
                a[1] = __float_as_uint(Asm[(r + 8) * 32 + cx0]);
                a[2] = __float_as_uint(Asm[r * 32 + cx1]);
                a[3] = __float_as_uint(Asm[(r + 8) * 32 + cx1]);
                uint32_t bb[2][2];
#pragma unroll
                for (int nt = 0; nt < 2; nt++) {
                    int n = nw * 16 + nt * 8 + l4;
                    bb[nt][0] = __float_as_uint(Bsm[n * 32 + cx0]);
                    bb[nt][1] = __float_as_uint(Bsm[n * 32 + cx1]);
                }
#pragma unroll
                for (int nt = 0; nt < 2; nt++)
                    mma8(accl[nt], a, bb[nt]);
            }
        }
#pragma unroll
        for (int nt = 0; nt < 2; nt++)
#pragma unroll
            for (int c = 0; c < 4; c++) accl[nt][c] *= 0.125f;

        // ---- chunk row-max partials ----
#pragma unroll
        for (int h = 0; h < 2; h++) {
            float m = fmaxf(fmaxf(accl[0][2 * h], accl[0][2 * h + 1]),
                            fmaxf(accl[1][2 * h], accl[1][2 * h + 1]));
            m = fmaxf(m, __shfl_xor_sync(0xffffffffu, m, 1));
            m = fmaxf(m, __shfl_xor_sync(0xffffffffu, m, 2));
            if (lm4 == 0) pmax[(mw * 16 + l4 + 8 * h) * 4 + nw] = m;
        }
        __syncthreads();

        // ---- P = exp(l - Mnew), rescale accg, partial sums, stage P ----
        float Mn_[2], f_[2];
#pragma unroll
        for (int h = 0; h < 2; h++) {
            int row = mw * 16 + l4 + 8 * h;
            float Mo = Mrun[row];
            float Mn = fmaxf(fmaxf(fmaxf(pmax[row * 4], pmax[row * 4 + 1]),
                                   fmaxf(pmax[row * 4 + 2], pmax[row * 4 + 3])), Mo);
            Mn_[h] = Mn; f_[h] = __expf(Mo - Mn);
        }
#pragma unroll
        for (int h = 0; h < 2; h++) {
            float s = 0.f;
#pragma unroll
            for (int nt = 0; nt < 2; nt++) {
                float p0 = __expf(accl[nt][2 * h]     - Mn_[h]);
                float p1 = __expf(accl[nt][2 * h + 1] - Mn_[h]);
                s += p0 + p1;
                accl[nt][2 * h] = p0; accl[nt][2 * h + 1] = p1;
            }
            s += __shfl_xor_sync(0xffffffffu, s, 1);
            s += __shfl_xor_sync(0xffffffffu, s, 2);
            if (lm4 == 0) psum[(mw * 16 + l4 + 8 * h) * 4 + nw] = s;
#pragma unroll
            for (int nt = 0; nt < 8; nt++) {
                accg[nt][2 * h]     *= f_[h];
                accg[nt][2 * h + 1] *= f_[h];
            }
        }
#pragma unroll
        for (int h = 0; h < 2; h++) {
            int row = mw * 16 + l4 + 8 * h;
#pragma unroll
            for (int nt = 0; nt < 2; nt++) {
                int col = nw * 16 + nt * 8 + 2 * lm4;
                int kp = col >> 5, kc = col & 31, kb = kc >> 2, lm = kc & 3;
                float2 v;
                v.x = rna_tf32(accl[nt][2 * h]);
                v.y = rna_tf32(accl[nt][2 * h + 1]);
                *(float2*)&Pt[kp * 2048 + row * 32 + ((kb ^ (row & 7)) << 2) + lm] = v;
            }
        }
        __syncthreads();

        // ---- update running stats ----
        if (t < 64) {
            float Mo = Mrun[t];
            float Mn = fmaxf(fmaxf(fmaxf(pmax[t * 4], pmax[t * 4 + 1]),
                                   fmaxf(pmax[t * 4 + 2], pmax[t * 4 + 3])), Mo);
            Lrun[t] = Lrun[t] * __expf(Mo - Mn) +
                      (psum[t * 4] + psum[t * 4 + 1] + psum[t * 4 + 2] + psum[t * 4 + 3]);
            Mrun[t] = Mn;
        }

        // ---- gobj mma: accg += P(16-row slice x K64) @ x(64-d slice x K64)^T
#pragma unroll
        for (int kp = 0; kp < 2; kp++) {
            const float* Asm = Pt + kp * 2048;
            const float* Bsm = sm + 16384 + sb * 16384 + kp * 8192;
#pragma unroll
            for (int ks = 0; ks < 4; ks++) {
                int cx0 = lm4 + ((((2 * ks) ^ l4) & 7) << 2);
                int cx1 = lm4 + ((((2 * ks + 1) ^ l4) & 7) << 2);
                uint32_t a[4];
                int r = mw * 16 + l4;
                a[0] = __float_as_uint(Asm[r * 32 + cx0]);
                a[1] = __float_as_uint(Asm[(r + 8) * 32 + cx0]);
                a[2] = __float_as_uint(Asm[r * 32 + cx1]);
                a[3] = __float_as_uint(Asm[(r + 8) * 32 + cx1]);
#pragma unroll
                for (int nt = 0; nt < 8; nt++) {
                    int n = nw * 64 + nt * 8 + l4;
                    uint32_t bb[2];
                    bb[0] = __float_as_uint(Bsm[n * 32 + cx0]);
                    bb[1] = __float_as_uint(Bsm[n * 32 + cx1]);
                    mma8(accg[nt], a, bb);
                }
            }
        }
        __syncthreads();
    }

    // ---- finalize: divide by L, rna, store ----
#pragma unroll
    for (int h = 0; h < 2; h++) {
        int row = mw * 16 + l4 + 8 * h;
        float inv = 1.0f / Lrun[row];
        long base = ((long)b * Qq + qt * 64 + row) * 256 + nw * 64;
#pragma unroll
        for (int nt = 0; nt < 8; nt++) {
            float2 v;
            v.x = rna_tf32(accg[nt][2 * h]     * inv);
            v.y = rna_tf32(accg[nt][2 * h + 1] * inv);
            *(float2*)&gobj[base + nt * 8 + 2 * lm4] = v;
        }
    }
}

// ---------------- fused zz GEMM + R reduction --------------------------------
__global__ __launch_bounds__(256, 2)
void zzR_kernel(const float* __restrict__ gobj, const float* __restrict__ wt2,
                float* __restrict__ R) {
    constexpr int BM = 96, STG = (BM + 128) * 32;
    constexpr int EST = 130;
    extern __shared__ float sm[];
    const uint32_t smb = smem_u32(sm);
    const int t = threadIdx.x;
    const int wid = t >> 5, lane = t & 31;
    const int l4 = lane >> 2, lm4 = lane & 3;
    const int mBase = (wid >> 2) * 48;
    const int nBase = (wid & 3) * 32;
    const int r = blockIdx.x;
    const int row0 = blockIdx.y * BM;

    const float* A  = gobj + (long)row0 * 256;
    const float* Bq = wt2 + (long)(r * 64) * 256;
    const float* Bk = wt2 + (long)(1024 + r * 64) * 256;

    auto load_stage = [&](int kt, int sb) {
        const int k0 = kt * 32;
        uint32_t ab = smb + sb * (STG * 4);
#pragma unroll
        for (int i = 0; i < 3; i++) {
            int id = t + i * 256;
            int row = id >> 3, kb = id & 7;
            uint32_t dst = ab + (uint32_t)((row * 32 + ((kb ^ (row & 7)) << 2)) * 4);
            cpa16(dst, A + (long)row * 256 + k0 + kb * 4);
        }
        uint32_t bb = ab + BM * 32 * 4;
#pragma unroll
        for (int i = 0; i < 4; i++) {
            int id = t + i * 256;
            int row = id >> 3, kb = id & 7;
            const float* src = (row < 64) ? (Bq + (long)row * 256)
                                          : (Bk + (long)(row - 64) * 256);
            uint32_t dst = bb + (uint32_t)((row * 32 + ((kb ^ (row & 7)) << 2)) * 4);
            cpa16(dst, src + k0 + kb * 4);
        }
        asm volatile("cp.async.commit_group;" ::: "memory");
    };

    float acc[3][4][4] = {};
    load_stage(0, 0);
    for (int kt = 0; kt < 8; kt++) {
        if (kt + 1 < 8) {
            load_stage(kt + 1, (kt + 1) & 1);
            asm volatile("cp.async.wait_group 1;" ::: "memory");
        } else {
            asm volatile("cp.async.wait_group 0;" ::: "memory");
        }
        __syncthreads();
        const float* As = sm + (kt & 1) * STG;
        const float* Bs = As + BM * 32;
#pragma unroll
        for (int ks = 0; ks < 4; ks++) {
            const int cx0 = lm4 + ((((2 * ks) ^ l4) & 7) << 2);
            const int cx1 = lm4 + ((((2 * ks + 1) ^ l4) & 7) << 2);
            uint32_t a[3][4];
#pragma unroll
            for (int mt = 0; mt < 3; mt++) {
                int rr = mBase + mt * 16 + l4;
                a[mt][0] = __float_as_uint(As[rr * 32 + cx0]);
                a[mt][1] = __float_as_uint(As[(rr + 8) * 32 + cx0]);
                a[mt][2] = __float_as_uint(As[rr * 32 + cx1]);
                a[mt][3] = __float_as_uint(As[(rr + 8) * 32 + cx1]);
            }
            uint32_t b[4][2];
#pragma unroll
            for (int nt = 0; nt < 4; nt++) {
                int n = nBase + nt * 8 + l4;
                b[nt][0] = __float_as_uint(Bs[n * 32 + cx0]);
                b[nt][1] = __float_as_uint(Bs[n * 32 + cx1]);
            }
#pragma unroll
            for (int mt = 0; mt < 3; mt++)
#pragma unroll
                for (int nt = 0; nt < 4; nt++)
                    mma8(acc[mt][nt], a[mt], b[nt]);
        }
        __syncthreads();
    }

    float* ep = sm;
#pragma unroll
    for (int mt = 0; mt < 3; mt++) {
#pragma unroll
        for (int h = 0; h < 2; h++) {
            int row = mBase + mt * 16 + l4 + 8 * h;
#pragma unroll
            for (int nt = 0; nt < 4; nt++) {
                int col = nBase + nt * 8 + 2 * lm4;
                ep[row * EST + col]     = acc[mt][nt][2 * h + 0];
                ep[row * EST + col + 1] = acc[mt][nt][2 * h + 1];
            }
        }
    }
    __syncthreads();

    const long bg0 = row0 / 3;
    float* Rout = R + (long)r * NBG * 9;
    for (int w = t; w < 288; w += 256) {
        int gl = w / 9, pr = w % 9;
        int nn = pr / 3, mm = pr % 3;
        const float* ra = ep + (gl * 3 + nn) * EST;
        const float* rb = ep + (gl * 3 + mm) * EST + 64;
        float sum = 0.f;
#pragma unroll
        for (int p = 0; p < 64; p++) sum += ra[p] * rb[p];
        Rout[(bg0 + gl) * 9 + pr] = sum;
    }
}

// ---------------- R * Fsym contraction ---------------------------------------
__global__ __launch_bounds__(64)
void rfin_kernel(const float* __restrict__ R, float* __restrict__ out) {
    __shared__ float Rs[144];
    const int bg = blockIdx.x, t = threadIdx.x;
    for (int i = t; i < 144; i += 64) {
        int pr = i >> 4, r = i & 15;
        Rs[i] = R[(long)r * NBG * 9 + (long)bg * 9 + pr];
    }
    __syncthreads();
    const float* f = g_fsym + t * 144;
    float acc = 0.f;
#pragma unroll 16
    for (int i = 0; i < 144; i++) acc += Rs[i] * f[i];
    out[(long)bg * 64 + t] = acc;
}

// ---------------- precompute kernels -----------------------------------------
__global__ void pe_kernel() {
    int idx = blockIdx.x * blockDim.x + threadIdx.x;
    if (idx >= Nn * KDc) return;
    int n = idx >> 6, j = idx & 63;
    float e = (float)(j & ~1) / 64.0f;
    float angle = (float)n / powf(10000.0f, e);
    double a = (double)angle;
    g_pe[idx] = (j & 1) ? (float)cos(a) : (float)sin(a);
}

__global__ void fsym_kernel(const float* __restrict__ filters) {
    int idx = blockIdx.x * blockDim.x + threadIdx.x;
    if (idx >= 64 * 144) return;
    int f = idx / 144, rem = idx % 144;
    int n = rem / 48, m = (rem / 16) % 3, r = rem & 15;
    const int P[6][3] = {{0,1,2},{0,2,1},{1,0,2},{1,2,0},{2,0,1},{2,1,0}};
    float s = 0.f;
#pragma unroll
    for (int p = 0; p < 6; p++)
        s += filters[f * 144 + P[p][n] * 48 + P[p][m] * 16 + r];
    g_fsym[idx] = s * (1.0f / 6.0f);
}

__global__ void wt2_kernel(const float* __restrict__ Wq, const float* __restrict__ Wk) {
    int idx = blockIdx.x * blockDim.x + threadIdx.x;
    if (idx >= 2048 * 256) return;
    int c = idx >> 8, d = idx & 255;
    const float* W = (c < 1024) ? Wq : Wk;
    int cc = c & 1023, r = cc >> 6, p = cc & 63;
    g_wt2[idx] = rna_tf32(W[(r << 14) + (d << 6) + p]);
}

__global__ void smallprep_kernel(const float* __restrict__ wkmap, const float* __restrict__ qe) {
    int idx = blockIdx.x * blockDim.x + threadIdx.x;
    if (idx < 64 * 256) {
        int kd = idx >> 8, d = idx & 255;
        g_wkT[idx] = rna_tf32(wkmap[d * 64 + kd]);
    }
    if (idx < Qq * KDc) g_qer[idx] = rna_tf32(qe[idx]);
}

// ---------------- launch -----------------------------------------------------
extern "C" void kernel_launch(void* const* d_in, const int* in_sizes, int n_in,
                              void* d_out, int out_size) {
    (void)in_sizes; (void)n_in; (void)out_size;
    const float* x       = (const float*)d_in[0];
    const float* filters = (const float*)d_in[1];
    const float* qe      = (const float*)d_in[2];
    const float* wkmap   = (const float*)d_in[3];
    const float* Wq      = (const float*)d_in[4];
    const float* Wk      = (const float*)d_in[5];
    float* out = (float*)d_out;

    float *pxT, *pk, *pg, *pR, *pwt2, *pwkT, *pqer;
    cudaGetSymbolAddress((void**)&pxT,  g_xT);
    cudaGetSymbolAddress((void**)&pk,   g_k);
    cudaGetSymbolAddress((void**)&pg,   g_gobj);
    cudaGetSymbolAddress((void**)&pR,   g_R);
    cudaGetSymbolAddress((void**)&pwt2, g_wt2);
    cudaGetSymbolAddress((void**)&pwkT, g_wkT);
    cudaGetSymbolAddress((void**)&pqer, g_qer);

    const int SM_KP   = 2 * (128 + 64) * 32 * 4;   // 49152
    const int SM_ZZR  = 2 * (96 + 128) * 32 * 4;   // 57344
    const int SM_ATTN = 49792 * 4;                 // 199168
    cudaFuncSetAttribute((const void*)mma_gemm<128, 64, 1, true, true>,
                         cudaFuncAttributeMaxDynamicSharedMemorySize, SM_KP);
    cudaFuncSetAttribute((const void*)attn_kernel,
                         cudaFuncAttributeMaxDynamicSharedMemorySize, SM_ATTN);
    cudaFuncSetAttribute((const void*)zzR_kernel,
                         cudaFuncAttributeMaxDynamicSharedMemorySize, SM_ZZR);

    // order chosen so the ncu capture window (historically the 4th launch)
    // lands on attn_kernel
    pe_kernel<<<(Nn * KDc + 255) / 256, 256>>>();
    smallprep_kernel<<<(64 * 256 + 255) / 256, 256>>>(wkmap, qe);

    // k = rna(x @ wkT^T + PE), also emits xT : M=131072, N=64, K=256
    mma_gemm<128, 64, 1, true, true><<<dim3(1, 1024, 1), 128, SM_KP>>>(
        x, pwkT, pk, 256, 64, 0, 0, 0, 1.0f);

    // fused logits + softmax + gobj : grid (3 q-tiles, 128 b), 512 threads
    attn_kernel<<<dim3(3, Bsz), 512, SM_ATTN>>>(pk, pxT, pqer, pg);

    wt2_kernel<<<(2048 * 256 + 255) / 256, 256>>>(Wq, Wk);
    fsym_kernel<<<(64 * 144 + 255) / 256, 256>>>(filters);

    // fused zz GEMM + R : grid (r=16, 256 slabs of 96 rows)
    zzR_kernel<<<dim3(RELD, 256, 1), 256, SM_ZZR>>>(pg, pwt2, pR);

    // out[bg][f] = sum_i R[bg][i] * Fsym[f][i]
    rfin_kernel<<<NBG, 64>>>(pR, out);
}